// round 2
// baseline (speedup 1.0000x reference)
#include <cuda_runtime.h>
#include <cuda_fp16.h>
#include <cstdint>

#define NUM_B 4
#define NUM_N 2048
#define NUM_K 48
#define DIM_H 128
#define DIM_IN 256
#define DIM_FF 512
#define NODES (NUM_B*NUM_N)        // 8192
#define NPB 2
#define MROWS (NPB*NUM_K)          // 96
#define NGROUPS (NODES/NPB)        // 4096

// smem leading dims (elements), chosen so fragment LDS is bank-conflict-free:
// bank = ((n*LD/2 + k/2) mod 32); LD/2 mod 32 == 4 -> 4*(lane/4)+(lane%4) pattern
#define LD_A  264
#define LD_W1 264
#define LD_S  136
#define LD_WF 520

// ---- kernel1 smem offsets (bytes) ----
#define K1_OFF_W1 0                // 128*264*2 = 67584
#define K1_OFF_W2 67584            // 128*136*2 = 34816
#define K1_OFF_W3 102400           // 34816
#define K1_OFF_A  137216           // 96*264*2  = 50688
#define K1_OFF_M  187904           // 96*136*2  = 26112
#define K1_OFF_B1 214016           // 512
#define K1_OFF_B2 214528
#define K1_OFF_B3 215040
#define K1_OFF_MS 215552           // 96*4 = 384
#define K1_OFF_IX 215936           // 96*4 = 384
#define K1_SMEM   216320

// ---- kernel2 smem ----
#define K2_OFF_A 0                 // 34816
#define K2_OFF_W 34816             // 34816
#define K2_OFF_B 69632             // 512
#define K2_SMEM  70144

// ---- kernel3 smem ----
#define K3_OFF_W 0                 // 128*520*2 = 133120
#define K3_OFF_A 133120            // 34816
#define K3_OFF_B 167936            // 512
#define K3_SMEM  168448

// scratch (no cudaMalloc allowed -> device globals)
__device__ float  g_h[NODES*DIM_H];            // h = h_V + dh  (fp32)
__device__ __half g_t[(size_t)NODES*DIM_FF];   // FFN intermediate (fp16)

__device__ __forceinline__ float gelu_tanh(float x){
    float x3 = x*x*x;
    return 0.5f*x*(1.0f + tanhf(0.7978845608028654f*(x + 0.044715f*x3)));
}
__device__ __forceinline__ float gelu_erf(float x){
    return 0.5f*x*(1.0f + erff(x*0.7071067811865475f));
}

__device__ __forceinline__ void mma_f16(float* c,
    uint32_t a0, uint32_t a1, uint32_t a2, uint32_t a3, uint32_t b0, uint32_t b1){
    asm volatile("mma.sync.aligned.m16n8k16.row.col.f32.f16.f16.f32 "
        "{%0,%1,%2,%3},{%4,%5,%6,%7},{%8,%9},{%0,%1,%2,%3};"
        : "+f"(c[0]), "+f"(c[1]), "+f"(c[2]), "+f"(c[3])
        : "r"(a0), "r"(a1), "r"(a2), "r"(a3), "r"(b0), "r"(b1));
}

// Warp computes rows [rowbase, rowbase+16*MTILES), cols [colbase, colbase+32).
// A: row-major [rows][LDA] fp16.  Bt: n-major (k contiguous) [n][LDB] fp16.
template<int MTILES, int KSTEPS, int LDA, int LDB>
__device__ __forceinline__ void gemm_frag(const __half* __restrict__ A,
                                          const __half* __restrict__ Bt,
                                          int rowbase, int colbase, int tg, int tk,
                                          float acc[][4][4]){
    for (int kt = 0; kt < KSTEPS; kt++){
        const int k0 = kt*16 + tk*2;
        uint32_t a[MTILES][4];
#pragma unroll
        for (int mt = 0; mt < MTILES; mt++){
            const __half* ap = A + (size_t)(rowbase + mt*16 + tg)*LDA + k0;
            a[mt][0] = *(const uint32_t*)(ap);
            a[mt][1] = *(const uint32_t*)(ap + 8*LDA);
            a[mt][2] = *(const uint32_t*)(ap + 8);
            a[mt][3] = *(const uint32_t*)(ap + 8*LDA + 8);
        }
#pragma unroll
        for (int nt = 0; nt < 4; nt++){
            const __half* bp = Bt + (size_t)(colbase + nt*8 + tg)*LDB + k0;
            uint32_t b0 = *(const uint32_t*)(bp);
            uint32_t b1 = *(const uint32_t*)(bp + 8);
#pragma unroll
            for (int mt = 0; mt < MTILES; mt++)
                mma_f16(acc[mt][nt], a[mt][0], a[mt][1], a[mt][2], a[mt][3], b0, b1);
        }
    }
}

// ============================================================================
// Kernel 1: persistent edge-MLP.  h = h_V + sum_k(mask*(MLP(h_EV)))/30
// ============================================================================
__global__ void __launch_bounds__(256, 1) enc_edge_kernel(
    const float* __restrict__ hV, const float* __restrict__ hE,
    const int* __restrict__ Eidx, const float* __restrict__ maskAtt,
    const float* __restrict__ W1, const float* __restrict__ b1,
    const float* __restrict__ W2, const float* __restrict__ b2,
    const float* __restrict__ W3, const float* __restrict__ b3)
{
    extern __shared__ unsigned char smem[];
    __half* sW1 = (__half*)(smem + K1_OFF_W1);
    __half* sW2 = (__half*)(smem + K1_OFF_W2);
    __half* sW3 = (__half*)(smem + K1_OFF_W3);
    __half* sA  = (__half*)(smem + K1_OFF_A);
    __half* sM  = (__half*)(smem + K1_OFF_M);
    float* sB1   = (float*)(smem + K1_OFF_B1);
    float* sB2   = (float*)(smem + K1_OFF_B2);
    float* sB3   = (float*)(smem + K1_OFF_B3);
    float* sMask = (float*)(smem + K1_OFF_MS);
    int*   sIdx  = (int*)  (smem + K1_OFF_IX);

    const int tid = threadIdx.x;

    // one-time weight load (transposed, fp16)
    for (int i = tid; i < DIM_IN*DIM_H; i += 256){
        int k = i >> 7, n = i & 127;
        sW1[n*LD_W1 + k] = __float2half_rn(W1[i]);
    }
    for (int i = tid; i < DIM_H*DIM_H; i += 256){
        int k = i >> 7, n = i & 127;
        sW2[n*LD_S + k] = __float2half_rn(W2[i]);
        sW3[n*LD_S + k] = __float2half_rn(W3[i]);
    }
    if (tid < 128){ sB1[tid] = b1[tid]; sB2[tid] = b2[tid]; sB3[tid] = b3[tid]; }

    const int lane = tid & 31, wid = tid >> 5;
    const int wm = wid >> 2, wn = wid & 3;      // 2 warp-rows x 4 warp-cols
    const int tg = lane >> 2, tk = lane & 3;
    const int colbase = wn*32;
    const int rowbase = wm*48;                  // warp wm owns one node's 48 rows

    for (int g = blockIdx.x; g < NGROUPS; g += gridDim.x){
        __syncthreads();   // previous iteration fully consumed sMask/sM/sA
        if (tid < MROWS){
            int node = g*NPB + tid/NUM_K;
            int kk = tid % NUM_K;
            sIdx[tid]  = Eidx[node*NUM_K + kk];
            sMask[tid] = maskAtt[node*NUM_K + kk];
        }
        __syncthreads();

        // gather + concat -> sA [96][256] fp16
        for (int i = tid; i < MROWS*64; i += 256){
            int r = i >> 6, c = i & 63;
            int node = g*NPB + r/NUM_K;
            float4 v;
            if (c < 32){
                int b  = node >> 11;
                int nb = (b << 11) + sIdx[r];
                v = ((const float4*)(hV + (size_t)nb*DIM_H))[c];
            } else {
                int kk = r % NUM_K;
                v = ((const float4*)(hE + (size_t)(node*NUM_K + kk)*DIM_H))[c - 32];
            }
            __half2 p0 = __floats2half2_rn(v.x, v.y);
            __half2 p1 = __floats2half2_rn(v.z, v.w);
            __half* dst = sA + (size_t)r*LD_A + c*4;
            *(uint32_t*)dst       = *(uint32_t*)&p0;
            *(uint32_t*)(dst + 2) = *(uint32_t*)&p1;
        }
        __syncthreads();

        float acc[3][4][4];

        // ---- GEMM1: [96,256]x[256,128] + gelu_tanh ----
#pragma unroll
        for (int mt = 0; mt < 3; mt++)
#pragma unroll
            for (int nt = 0; nt < 4; nt++)
#pragma unroll
                for (int j = 0; j < 4; j++) acc[mt][nt][j] = 0.f;
        gemm_frag<3,16,LD_A,LD_W1>(sA, sW1, rowbase, colbase, tg, tk, acc);
#pragma unroll
        for (int nt = 0; nt < 4; nt++){
            int col = colbase + nt*8 + tk*2;
            float bb0 = sB1[col], bb1 = sB1[col+1];
#pragma unroll
            for (int mt = 0; mt < 3; mt++){
                int row = rowbase + mt*16 + tg;
                __half2 p0 = __floats2half2_rn(gelu_tanh(acc[mt][nt][0]+bb0),
                                               gelu_tanh(acc[mt][nt][1]+bb1));
                __half2 p1 = __floats2half2_rn(gelu_tanh(acc[mt][nt][2]+bb0),
                                               gelu_tanh(acc[mt][nt][3]+bb1));
                *(uint32_t*)(sM + (size_t)row*LD_S + col)     = *(uint32_t*)&p0;
                *(uint32_t*)(sM + (size_t)(row+8)*LD_S + col) = *(uint32_t*)&p1;
            }
        }
        __syncthreads();

        // ---- GEMM2: [96,128]x[128,128] + gelu_tanh ----
#pragma unroll
        for (int mt = 0; mt < 3; mt++)
#pragma unroll
            for (int nt = 0; nt < 4; nt++)
#pragma unroll
                for (int j = 0; j < 4; j++) acc[mt][nt][j] = 0.f;
        gemm_frag<3,8,LD_S,LD_S>(sM, sW2, rowbase, colbase, tg, tk, acc);
        __syncthreads();   // all reads of sM done before overwrite
#pragma unroll
        for (int nt = 0; nt < 4; nt++){
            int col = colbase + nt*8 + tk*2;
            float bb0 = sB2[col], bb1 = sB2[col+1];
#pragma unroll
            for (int mt = 0; mt < 3; mt++){
                int row = rowbase + mt*16 + tg;
                __half2 p0 = __floats2half2_rn(gelu_tanh(acc[mt][nt][0]+bb0),
                                               gelu_tanh(acc[mt][nt][1]+bb1));
                __half2 p1 = __floats2half2_rn(gelu_tanh(acc[mt][nt][2]+bb0),
                                               gelu_tanh(acc[mt][nt][3]+bb1));
                *(uint32_t*)(sM + (size_t)row*LD_S + col)     = *(uint32_t*)&p0;
                *(uint32_t*)(sM + (size_t)(row+8)*LD_S + col) = *(uint32_t*)&p1;
            }
        }
        __syncthreads();

        // ---- GEMM3 + masked K-reduction + residual ----
#pragma unroll
        for (int mt = 0; mt < 3; mt++)
#pragma unroll
            for (int nt = 0; nt < 4; nt++)
#pragma unroll
                for (int j = 0; j < 4; j++) acc[mt][nt][j] = 0.f;
        gemm_frag<3,8,LD_S,LD_S>(sM, sW3, rowbase, colbase, tg, tk, acc);

        float red[4][2];
#pragma unroll
        for (int nt = 0; nt < 4; nt++){ red[nt][0] = 0.f; red[nt][1] = 0.f; }
#pragma unroll
        for (int mt = 0; mt < 3; mt++){
            int row = rowbase + mt*16 + tg;
            float m0 = sMask[row], m1 = sMask[row+8];
#pragma unroll
            for (int nt = 0; nt < 4; nt++){
                int col = colbase + nt*8 + tk*2;
                float bc0 = sB3[col], bc1 = sB3[col+1];
                red[nt][0] += (acc[mt][nt][0]+bc0)*m0 + (acc[mt][nt][2]+bc0)*m1;
                red[nt][1] += (acc[mt][nt][1]+bc1)*m0 + (acc[mt][nt][3]+bc1)*m1;
            }
        }
#pragma unroll
        for (int off = 4; off < 32; off <<= 1){
#pragma unroll
            for (int nt = 0; nt < 4; nt++){
                red[nt][0] += __shfl_xor_sync(0xffffffffu, red[nt][0], off);
                red[nt][1] += __shfl_xor_sync(0xffffffffu, red[nt][1], off);
            }
        }
        if (tg == 0){
            int node = g*NPB + wm;
#pragma unroll
            for (int nt = 0; nt < 4; nt++){
                int col = colbase + nt*8 + tk*2;
                g_h[node*DIM_H + col]     = hV[node*DIM_H + col]     + red[nt][0]*(1.0f/30.0f);
                g_h[node*DIM_H + col + 1] = hV[node*DIM_H + col + 1] + red[nt][1]*(1.0f/30.0f);
            }
        }
    }
}

// ============================================================================
// Kernel 2: t = gelu_exact(h @ W_in + b_in)   [8192,128]x[128,512]
// ============================================================================
__global__ void __launch_bounds__(256) ffn1_kernel(const float* __restrict__ Win,
                                                   const float* __restrict__ bin)
{
    extern __shared__ unsigned char smem[];
    __half* sA = (__half*)(smem + K2_OFF_A);
    __half* sW = (__half*)(smem + K2_OFF_W);
    float* sB = (float*)(smem + K2_OFF_B);

    const int tid = threadIdx.x;
    const int rowb = blockIdx.x*128;
    const int nb   = blockIdx.y*128;

    for (int i = tid; i < 128*128; i += 256){
        int k = i >> 7, n = i & 127;
        sW[n*LD_S + k] = __float2half_rn(Win[(size_t)k*DIM_FF + nb + n]);
    }
    if (tid < 128) sB[tid] = bin[nb + tid];
    for (int i = tid; i < 128*32; i += 256){
        int r = i >> 5, c = i & 31;
        float4 v = ((const float4*)(g_h + (size_t)(rowb + r)*DIM_H))[c];
        __half2 p0 = __floats2half2_rn(v.x, v.y);
        __half2 p1 = __floats2half2_rn(v.z, v.w);
        __half* dst = sA + (size_t)r*LD_S + c*4;
        *(uint32_t*)dst       = *(uint32_t*)&p0;
        *(uint32_t*)(dst + 2) = *(uint32_t*)&p1;
    }
    __syncthreads();

    const int lane = tid & 31, wid = tid >> 5;
    const int wm = wid >> 2, wn = wid & 3;
    const int tg = lane >> 2, tk = lane & 3;

    float acc[4][4][4];
#pragma unroll
    for (int mt = 0; mt < 4; mt++)
#pragma unroll
        for (int nt = 0; nt < 4; nt++)
#pragma unroll
            for (int j = 0; j < 4; j++) acc[mt][nt][j] = 0.f;
    gemm_frag<4,8,LD_S,LD_S>(sA, sW, wm*64, wn*32, tg, tk, acc);

#pragma unroll
    for (int nt = 0; nt < 4; nt++){
        int col = wn*32 + nt*8 + tk*2;
        float bb0 = sB[col], bb1 = sB[col+1];
#pragma unroll
        for (int mt = 0; mt < 4; mt++){
            int row = rowb + wm*64 + mt*16 + tg;
            __half2 p0 = __floats2half2_rn(gelu_erf(acc[mt][nt][0]+bb0),
                                           gelu_erf(acc[mt][nt][1]+bb1));
            __half2 p1 = __floats2half2_rn(gelu_erf(acc[mt][nt][2]+bb0),
                                           gelu_erf(acc[mt][nt][3]+bb1));
            *(__half2*)(g_t + (size_t)row*DIM_FF + nb + col)     = p0;
            *(__half2*)(g_t + (size_t)(row+8)*DIM_FF + nb + col) = p1;
        }
    }
}

// ============================================================================
// Kernel 3: out = mask_V * (h + t @ W_out + b_out)   [8192,512]x[512,128]
// ============================================================================
__global__ void __launch_bounds__(256) ffn2_kernel(const float* __restrict__ Wout,
                                                   const float* __restrict__ bout,
                                                   const float* __restrict__ maskV,
                                                   float* __restrict__ out)
{
    extern __shared__ unsigned char smem[];
    __half* sW = (__half*)(smem + K3_OFF_W);
    __half* sA = (__half*)(smem + K3_OFF_A);
    float* sB = (float*)(smem + K3_OFF_B);

    const int tid = threadIdx.x;
    const int rowb = blockIdx.x*128;

    for (int i = tid; i < DIM_FF*DIM_H; i += 256){
        int k = i >> 7, n = i & 127;
        sW[(size_t)n*LD_WF + k] = __float2half_rn(Wout[(size_t)k*DIM_H + n]);
    }
    if (tid < 128) sB[tid] = bout[tid];

    const int lane = tid & 31, wid = tid >> 5;
    const int wm = wid >> 2, wn = wid & 3;
    const int tg = lane >> 2, tk = lane & 3;

    float acc[4][4][4];
#pragma unroll
    for (int mt = 0; mt < 4; mt++)
#pragma unroll
        for (int nt = 0; nt < 4; nt++)
#pragma unroll
            for (int j = 0; j < 4; j++) acc[mt][nt][j] = 0.f;

    for (int kc = 0; kc < 4; kc++){
        __syncthreads();
        for (int i = tid; i < 128*16; i += 256){
            int r = i >> 4, c = i & 15;
            uint4 v = ((const uint4*)(g_t + (size_t)(rowb + r)*DIM_FF + kc*128))[c];
            *(uint4*)(sA + (size_t)r*LD_S + c*8) = v;
        }
        __syncthreads();
        gemm_frag<4,8,LD_S,LD_WF>(sA, sW + kc*128, wm*64, wn*32, tg, tk, acc);
    }

#pragma unroll
    for (int nt = 0; nt < 4; nt++){
        int col = wn*32 + nt*8 + tk*2;
        float bb0 = sB[col], bb1 = sB[col+1];
#pragma unroll
        for (int mt = 0; mt < 4; mt++){
            int row = rowb + wm*64 + mt*16 + tg;
            float mv0 = maskV[row], mv1 = maskV[row+8];
            out[(size_t)row*DIM_H + col]       = mv0*(g_h[(size_t)row*DIM_H + col]       + acc[mt][nt][0] + bb0);
            out[(size_t)row*DIM_H + col + 1]   = mv0*(g_h[(size_t)row*DIM_H + col + 1]   + acc[mt][nt][1] + bb1);
            out[(size_t)(row+8)*DIM_H + col]   = mv1*(g_h[(size_t)(row+8)*DIM_H + col]   + acc[mt][nt][2] + bb0);
            out[(size_t)(row+8)*DIM_H + col+1] = mv1*(g_h[(size_t)(row+8)*DIM_H + col+1] + acc[mt][nt][3] + bb1);
        }
    }
}

// ============================================================================
extern "C" void kernel_launch(void* const* d_in, const int* in_sizes, int n_in,
                              void* d_out, int out_size)
{
    const float* hV      = (const float*)d_in[0];
    const float* hE      = (const float*)d_in[1];
    const int*   Eidx    = (const int*)  d_in[2];
    const float* maskV   = (const float*)d_in[3];
    const float* maskAtt = (const float*)d_in[4];
    const float* W1  = (const float*)d_in[5];
    const float* b1  = (const float*)d_in[6];
    const float* W2  = (const float*)d_in[7];
    const float* b2  = (const float*)d_in[8];
    const float* W3  = (const float*)d_in[9];
    const float* b3  = (const float*)d_in[10];
    const float* Win = (const float*)d_in[11];
    const float* bin = (const float*)d_in[12];
    const float* Wout= (const float*)d_in[13];
    const float* bout= (const float*)d_in[14];
    float* out = (float*)d_out;

    cudaFuncSetAttribute(enc_edge_kernel, cudaFuncAttributeMaxDynamicSharedMemorySize, K1_SMEM);
    cudaFuncSetAttribute(ffn1_kernel,     cudaFuncAttributeMaxDynamicSharedMemorySize, K2_SMEM);
    cudaFuncSetAttribute(ffn2_kernel,     cudaFuncAttributeMaxDynamicSharedMemorySize, K3_SMEM);

    enc_edge_kernel<<<148, 256, K1_SMEM>>>(hV, hE, Eidx, maskAtt,
                                           W1, b1, W2, b2, W3, b3);
    ffn1_kernel<<<dim3(64, 4), 256, K2_SMEM>>>(Win, bin);
    ffn2_kernel<<<64, 256, K3_SMEM>>>(Wout, bout, maskV, out);
}

// round 4
// speedup vs baseline: 1.2207x; 1.2207x over previous
#include <cuda_runtime.h>
#include <cuda_fp16.h>
#include <cstdint>

#define NUM_B 4
#define NUM_N 2048
#define NUM_K 48
#define DIM_H 128
#define DIM_IN 256
#define DIM_FF 512
#define NODES (NUM_B*NUM_N)        // 8192
#define NPB 2
#define MROWS (NPB*NUM_K)          // 96
#define NGROUPS (NODES/NPB)        // 4096

// smem leading dims (elements): LD*2 bytes mod 128 == 16 -> 8-row ldmatrix
// phases hit banks {0,4,8,...,28}+span -> conflict-free
#define LD_A  264
#define LD_W1 264
#define LD_S  136
#define LD_WF 520

// ---- kernel1 smem offsets (bytes) ----
#define K1_OFF_W1 0                // 128*264*2 = 67584
#define K1_OFF_W2 67584            // 128*136*2 = 34816
#define K1_OFF_W3 102400           // 34816
#define K1_OFF_A  137216           // 96*264*2  = 50688
#define K1_OFF_M  187904           // 96*136*2  = 26112
#define K1_OFF_B1 214016           // 512
#define K1_OFF_B2 214528
#define K1_OFF_B3 215040
#define K1_OFF_MS 215552           // 96*4
#define K1_OFF_IX 215936           // 96*4
#define K1_SMEM   216320

// ---- kernel2 smem ----
#define K2_OFF_A 0                 // 128*136*2 = 34816
#define K2_OFF_W 34816             // 34816
#define K2_OFF_B 69632             // 512
#define K2_SMEM  70144

// ---- kernel3 smem (64-row tiles) ----
#define K3_OFF_W 0                 // 128*520*2 = 133120
#define K3_OFF_A 133120            // 64*136*2 = 17408
#define K3_OFF_B 150528            // 512
#define K3_SMEM  151040

// scratch (no cudaMalloc allowed -> device globals)
__device__ float  g_h[NODES*DIM_H];            // h = h_V + dh  (fp32)
__device__ __half g_t[(size_t)NODES*DIM_FF];   // FFN intermediate (fp16)

__device__ __forceinline__ float gelu_tanh(float x){
    float x3 = x*x*x;
    return 0.5f*x*(1.0f + tanhf(0.7978845608028654f*(x + 0.044715f*x3)));
}
__device__ __forceinline__ float gelu_erf(float x){
    return 0.5f*x*(1.0f + erff(x*0.7071067811865475f));
}

__device__ __forceinline__ uint32_t smem_u32(const void* p){
    return (uint32_t)__cvta_generic_to_shared(p);
}

__device__ __forceinline__ void mma_f16(float* c,
    uint32_t a0, uint32_t a1, uint32_t a2, uint32_t a3, uint32_t b0, uint32_t b1){
    asm volatile("mma.sync.aligned.m16n8k16.row.col.f32.f16.f16.f32 "
        "{%0,%1,%2,%3},{%4,%5,%6,%7},{%8,%9},{%0,%1,%2,%3};"
        : "+f"(c[0]), "+f"(c[1]), "+f"(c[2]), "+f"(c[3])
        : "r"(a0), "r"(a1), "r"(a2), "r"(a3), "r"(b0), "r"(b1));
}

__device__ __forceinline__ void ldsm_x4(uint32_t& r0, uint32_t& r1, uint32_t& r2, uint32_t& r3,
                                        uint32_t addr){
    asm volatile("ldmatrix.sync.aligned.m8n8.x4.shared.b16 {%0,%1,%2,%3},[%4];"
        : "=r"(r0), "=r"(r1), "=r"(r2), "=r"(r3) : "r"(addr));
}

// ldmatrix-based warp GEMM fragment.
// aAddr: per-lane smem byte addr of A[(rowbase + (lane&15))*LDA + (lane>>4)*8]
// bAddr: per-lane smem byte addr of Bt[(colbase + (lane&7)+(lane>>4)*8)*LDB + ((lane>>3)&1)*8]
// acc: flattened [MT][2*NG][4]
template<int MT, int NG, int KSTEPS, int LDA, int LDB>
__device__ __forceinline__ void gemm_lm(uint32_t aAddr, uint32_t bAddr, float (*acc)[4]){
#pragma unroll
    for (int kt = 0; kt < KSTEPS; kt++){
        uint32_t a[MT][4], b[NG][4];
#pragma unroll
        for (int mt = 0; mt < MT; mt++)
            ldsm_x4(a[mt][0], a[mt][1], a[mt][2], a[mt][3],
                    aAddr + mt*(16*LDA*2) + kt*32);
#pragma unroll
        for (int g = 0; g < NG; g++)
            ldsm_x4(b[g][0], b[g][1], b[g][2], b[g][3],
                    bAddr + g*(16*LDB*2) + kt*32);
#pragma unroll
        for (int g = 0; g < NG; g++)
#pragma unroll
            for (int mt = 0; mt < MT; mt++){
                mma_f16(acc[mt*2*NG + 2*g    ], a[mt][0], a[mt][1], a[mt][2], a[mt][3], b[g][0], b[g][1]);
                mma_f16(acc[mt*2*NG + 2*g + 1], a[mt][0], a[mt][1], a[mt][2], a[mt][3], b[g][2], b[g][3]);
            }
    }
}

// ============================================================================
// Kernel 1: persistent edge-MLP.  h = h_V + sum_k(mask*(MLP(h_EV)))/30
// 512 threads: warp grid 2 (node) x 8 (16-col groups)
// ============================================================================
__global__ void __launch_bounds__(512, 1) enc_edge_kernel(
    const float* __restrict__ hV, const float* __restrict__ hE,
    const int* __restrict__ Eidx, const float* __restrict__ maskAtt,
    const float* __restrict__ W1, const float* __restrict__ b1,
    const float* __restrict__ W2, const float* __restrict__ b2,
    const float* __restrict__ W3, const float* __restrict__ b3)
{
    extern __shared__ unsigned char smem[];
    __half* sW1 = (__half*)(smem + K1_OFF_W1);
    __half* sW2 = (__half*)(smem + K1_OFF_W2);
    __half* sW3 = (__half*)(smem + K1_OFF_W3);
    __half* sA  = (__half*)(smem + K1_OFF_A);
    __half* sM  = (__half*)(smem + K1_OFF_M);
    float* sB1   = (float*)(smem + K1_OFF_B1);
    float* sB2   = (float*)(smem + K1_OFF_B2);
    float* sB3   = (float*)(smem + K1_OFF_B3);
    float* sMask = (float*)(smem + K1_OFF_MS);
    int*   sIdx  = (int*)  (smem + K1_OFF_IX);

    const int tid = threadIdx.x;

    // one-time weight load (transposed, fp16)
    for (int i = tid; i < DIM_IN*DIM_H; i += 512){
        int k = i >> 7, n = i & 127;
        sW1[n*LD_W1 + k] = __float2half_rn(W1[i]);
    }
    for (int i = tid; i < DIM_H*DIM_H; i += 512){
        int k = i >> 7, n = i & 127;
        sW2[n*LD_S + k] = __float2half_rn(W2[i]);
        sW3[n*LD_S + k] = __float2half_rn(W3[i]);
    }
    if (tid < 128){ sB1[tid] = b1[tid]; sB2[tid] = b2[tid]; sB3[tid] = b3[tid]; }

    const int lane = tid & 31, wid = tid >> 5;
    const int wm = wid >> 3, wn = wid & 7;      // 2 warp-rows x 8 warp-cols
    const int tg = lane >> 2, tk = lane & 3;
    const int colbase = wn*16;
    const int rowbase = wm*48;                  // warp-row wm owns one node's 48 rows

    // per-lane ldmatrix base addresses (fixed for the whole persistent loop)
    const int l15 = lane & 15, lhi = lane >> 4;
    const int b_n = (lane & 7) + lhi*8;
    const int b_k = ((lane >> 3) & 1) * 8;
    const uint32_t aA  = smem_u32(sA)  + (uint32_t)(((rowbase + l15)*LD_A  + lhi*8)*2);
    const uint32_t aM  = smem_u32(sM)  + (uint32_t)(((rowbase + l15)*LD_S  + lhi*8)*2);
    const uint32_t bW1 = smem_u32(sW1) + (uint32_t)(((colbase + b_n)*LD_W1 + b_k)*2);
    const uint32_t bW2 = smem_u32(sW2) + (uint32_t)(((colbase + b_n)*LD_S  + b_k)*2);
    const uint32_t bW3 = smem_u32(sW3) + (uint32_t)(((colbase + b_n)*LD_S  + b_k)*2);

    for (int g = blockIdx.x; g < NGROUPS; g += gridDim.x){
        __syncthreads();   // previous iteration fully consumed sMask/sM/sA
        if (tid < MROWS){
            int node = g*NPB + tid/NUM_K;
            int kk = tid % NUM_K;
            sIdx[tid]  = Eidx[node*NUM_K + kk];
            sMask[tid] = maskAtt[node*NUM_K + kk];
        }
        __syncthreads();

        // gather + concat -> sA [96][256] fp16
        for (int i = tid; i < MROWS*64; i += 512){
            int r = i >> 6, c = i & 63;
            int node = g*NPB + r/NUM_K;
            float4 v;
            if (c < 32){
                int b  = node >> 11;
                int nb = (b << 11) + sIdx[r];
                v = ((const float4*)(hV + (size_t)nb*DIM_H))[c];
            } else {
                int kk = r % NUM_K;
                v = ((const float4*)(hE + (size_t)(node*NUM_K + kk)*DIM_H))[c - 32];
            }
            __half2 p0 = __floats2half2_rn(v.x, v.y);
            __half2 p1 = __floats2half2_rn(v.z, v.w);
            __half* dst = sA + (size_t)r*LD_A + c*4;
            *(uint32_t*)dst       = *(uint32_t*)&p0;
            *(uint32_t*)(dst + 2) = *(uint32_t*)&p1;
        }
        __syncthreads();

        float acc[3][2][4];

        // ---- GEMM1: [96,256]x[256,128] + gelu_tanh ----
#pragma unroll
        for (int mt = 0; mt < 3; mt++)
#pragma unroll
            for (int nt = 0; nt < 2; nt++)
#pragma unroll
                for (int j = 0; j < 4; j++) acc[mt][nt][j] = 0.f;
        gemm_lm<3,1,16,LD_A,LD_W1>(aA, bW1, &acc[0][0]);
#pragma unroll
        for (int nt = 0; nt < 2; nt++){
            int col = colbase + nt*8 + tk*2;
            float bb0 = sB1[col], bb1 = sB1[col+1];
#pragma unroll
            for (int mt = 0; mt < 3; mt++){
                int row = rowbase + mt*16 + tg;
                __half2 p0 = __floats2half2_rn(gelu_tanh(acc[mt][nt][0]+bb0),
                                               gelu_tanh(acc[mt][nt][1]+bb1));
                __half2 p1 = __floats2half2_rn(gelu_tanh(acc[mt][nt][2]+bb0),
                                               gelu_tanh(acc[mt][nt][3]+bb1));
                *(uint32_t*)(sM + (size_t)row*LD_S + col)     = *(uint32_t*)&p0;
                *(uint32_t*)(sM + (size_t)(row+8)*LD_S + col) = *(uint32_t*)&p1;
            }
        }
        __syncthreads();

        // ---- GEMM2: [96,128]x[128,128] + gelu_tanh ----
#pragma unroll
        for (int mt = 0; mt < 3; mt++)
#pragma unroll
            for (int nt = 0; nt < 2; nt++)
#pragma unroll
                for (int j = 0; j < 4; j++) acc[mt][nt][j] = 0.f;
        gemm_lm<3,1,8,LD_S,LD_S>(aM, bW2, &acc[0][0]);
        __syncthreads();   // all reads of sM done before overwrite
#pragma unroll
        for (int nt = 0; nt < 2; nt++){
            int col = colbase + nt*8 + tk*2;
            float bb0 = sB2[col], bb1 = sB2[col+1];
#pragma unroll
            for (int mt = 0; mt < 3; mt++){
                int row = rowbase + mt*16 + tg;
                __half2 p0 = __floats2half2_rn(gelu_tanh(acc[mt][nt][0]+bb0),
                                               gelu_tanh(acc[mt][nt][1]+bb1));
                __half2 p1 = __floats2half2_rn(gelu_tanh(acc[mt][nt][2]+bb0),
                                               gelu_tanh(acc[mt][nt][3]+bb1));
                *(uint32_t*)(sM + (size_t)row*LD_S + col)     = *(uint32_t*)&p0;
                *(uint32_t*)(sM + (size_t)(row+8)*LD_S + col) = *(uint32_t*)&p1;
            }
        }
        __syncthreads();

        // ---- GEMM3 + masked K-reduction + residual ----
#pragma unroll
        for (int mt = 0; mt < 3; mt++)
#pragma unroll
            for (int nt = 0; nt < 2; nt++)
#pragma unroll
                for (int j = 0; j < 4; j++) acc[mt][nt][j] = 0.f;
        gemm_lm<3,1,8,LD_S,LD_S>(aM, bW3, &acc[0][0]);

        float red[2][2];
#pragma unroll
        for (int nt = 0; nt < 2; nt++){ red[nt][0] = 0.f; red[nt][1] = 0.f; }
#pragma unroll
        for (int mt = 0; mt < 3; mt++){
            int row = rowbase + mt*16 + tg;
            float m0 = sMask[row], m1 = sMask[row+8];
#pragma unroll
            for (int nt = 0; nt < 2; nt++){
                int col = colbase + nt*8 + tk*2;
                float bc0 = sB3[col], bc1 = sB3[col+1];
                red[nt][0] += (acc[mt][nt][0]+bc0)*m0 + (acc[mt][nt][2]+bc0)*m1;
                red[nt][1] += (acc[mt][nt][1]+bc1)*m0 + (acc[mt][nt][3]+bc1)*m1;
            }
        }
#pragma unroll
        for (int off = 4; off < 32; off <<= 1){
#pragma unroll
            for (int nt = 0; nt < 2; nt++){
                red[nt][0] += __shfl_xor_sync(0xffffffffu, red[nt][0], off);
                red[nt][1] += __shfl_xor_sync(0xffffffffu, red[nt][1], off);
            }
        }
        if (tg == 0){
            int node = g*NPB + wm;
#pragma unroll
            for (int nt = 0; nt < 2; nt++){
                int col = colbase + nt*8 + tk*2;
                g_h[node*DIM_H + col]     = hV[node*DIM_H + col]     + red[nt][0]*(1.0f/30.0f);
                g_h[node*DIM_H + col + 1] = hV[node*DIM_H + col + 1] + red[nt][1]*(1.0f/30.0f);
            }
        }
    }
}

// ============================================================================
// Kernel 2: t = gelu_exact(h @ W_in + b_in)   [8192,128]x[128,512]
// ============================================================================
__global__ void __launch_bounds__(256) ffn1_kernel(const float* __restrict__ Win,
                                                   const float* __restrict__ bin)
{
    extern __shared__ unsigned char smem[];
    __half* sA = (__half*)(smem + K2_OFF_A);
    __half* sW = (__half*)(smem + K2_OFF_W);
    float* sB = (float*)(smem + K2_OFF_B);

    const int tid = threadIdx.x;
    const int rowb = blockIdx.x*128;
    const int nb   = blockIdx.y*128;

    for (int i = tid; i < 128*128; i += 256){
        int k = i >> 7, n = i & 127;
        sW[n*LD_S + k] = __float2half_rn(Win[(size_t)k*DIM_FF + nb + n]);
    }
    if (tid < 128) sB[tid] = bin[nb + tid];
    for (int i = tid; i < 128*32; i += 256){
        int r = i >> 5, c = i & 31;
        float4 v = ((const float4*)(g_h + (size_t)(rowb + r)*DIM_H))[c];
        __half2 p0 = __floats2half2_rn(v.x, v.y);
        __half2 p1 = __floats2half2_rn(v.z, v.w);
        __half* dst = sA + (size_t)r*LD_S + c*4;
        *(uint32_t*)dst       = *(uint32_t*)&p0;
        *(uint32_t*)(dst + 2) = *(uint32_t*)&p1;
    }
    __syncthreads();

    const int lane = tid & 31, wid = tid >> 5;
    const int wm = wid >> 2, wn = wid & 3;
    const int tg = lane >> 2, tk = lane & 3;
    const int l15 = lane & 15, lhi = lane >> 4;
    const int b_n = (lane & 7) + lhi*8;
    const int b_k = ((lane >> 3) & 1) * 8;
    const uint32_t aA = smem_u32(sA) + (uint32_t)(((wm*64 + l15)*LD_S + lhi*8)*2);
    const uint32_t bW = smem_u32(sW) + (uint32_t)(((wn*32 + b_n)*LD_S + b_k)*2);

    float acc[4][4][4];
#pragma unroll
    for (int mt = 0; mt < 4; mt++)
#pragma unroll
        for (int nt = 0; nt < 4; nt++)
#pragma unroll
            for (int j = 0; j < 4; j++) acc[mt][nt][j] = 0.f;
    gemm_lm<4,2,8,LD_S,LD_S>(aA, bW, &acc[0][0]);

#pragma unroll
    for (int nt = 0; nt < 4; nt++){
        int col = wn*32 + nt*8 + tk*2;
        float bb0 = sB[col], bb1 = sB[col+1];
#pragma unroll
        for (int mt = 0; mt < 4; mt++){
            int row = rowb + wm*64 + mt*16 + tg;
            __half2 p0 = __floats2half2_rn(gelu_erf(acc[mt][nt][0]+bb0),
                                           gelu_erf(acc[mt][nt][1]+bb1));
            __half2 p1 = __floats2half2_rn(gelu_erf(acc[mt][nt][2]+bb0),
                                           gelu_erf(acc[mt][nt][3]+bb1));
            *(__half2*)(g_t + (size_t)row*DIM_FF + nb + col)     = p0;
            *(__half2*)(g_t + (size_t)(row+8)*DIM_FF + nb + col) = p1;
        }
    }
}

// ============================================================================
// Kernel 3: out = mask_V * (h + t @ W_out + b_out)   [8192,512]x[512,128]
// 128 CTAs x 64 rows
// ============================================================================
__global__ void __launch_bounds__(256) ffn2_kernel(const float* __restrict__ Wout,
                                                   const float* __restrict__ bout,
                                                   const float* __restrict__ maskV,
                                                   float* __restrict__ out)
{
    extern __shared__ unsigned char smem[];
    __half* sW = (__half*)(smem + K3_OFF_W);
    __half* sA = (__half*)(smem + K3_OFF_A);
    float* sB = (float*)(smem + K3_OFF_B);

    const int tid = threadIdx.x;
    const int rowb = blockIdx.x*64;

    for (int i = tid; i < DIM_FF*DIM_H; i += 256){
        int k = i >> 7, n = i & 127;
        sW[(size_t)n*LD_WF + k] = __float2half_rn(Wout[(size_t)k*DIM_H + n]);
    }
    if (tid < 128) sB[tid] = bout[tid];

    const int lane = tid & 31, wid = tid >> 5;
    const int wm = wid >> 2, wn = wid & 3;
    const int tg = lane >> 2, tk = lane & 3;
    const int l15 = lane & 15, lhi = lane >> 4;
    const int b_n = (lane & 7) + lhi*8;
    const int b_k = ((lane >> 3) & 1) * 8;
    const uint32_t aA = smem_u32(sA) + (uint32_t)(((wm*32 + l15)*LD_S + lhi*8)*2);
    const uint32_t bW = smem_u32(sW) + (uint32_t)(((wn*32 + b_n)*LD_WF + b_k)*2);

    float acc[2][4][4];
#pragma unroll
    for (int mt = 0; mt < 2; mt++)
#pragma unroll
        for (int nt = 0; nt < 4; nt++)
#pragma unroll
            for (int j = 0; j < 4; j++) acc[mt][nt][j] = 0.f;

    for (int kc = 0; kc < 4; kc++){
        __syncthreads();
        for (int i = tid; i < 64*16; i += 256){
            int r = i >> 4, c = i & 15;
            uint4 v = ((const uint4*)(g_t + (size_t)(rowb + r)*DIM_FF + kc*128))[c];
            *(uint4*)(sA + (size_t)r*LD_S + c*8) = v;
        }
        __syncthreads();
        gemm_lm<2,2,8,LD_S,LD_WF>(aA, bW + kc*128*2, &acc[0][0]);
    }

#pragma unroll
    for (int nt = 0; nt < 4; nt++){
        int col = wn*32 + nt*8 + tk*2;
        float bb0 = sB[col], bb1 = sB[col+1];
#pragma unroll
        for (int mt = 0; mt < 2; mt++){
            int row = rowb + wm*32 + mt*16 + tg;
            float mv0 = maskV[row], mv1 = maskV[row+8];
            out[(size_t)row*DIM_H + col]       = mv0*(g_h[(size_t)row*DIM_H + col]       + acc[mt][nt][0] + bb0);
            out[(size_t)row*DIM_H + col + 1]   = mv0*(g_h[(size_t)row*DIM_H + col + 1]   + acc[mt][nt][1] + bb1);
            out[(size_t)(row+8)*DIM_H + col]   = mv1*(g_h[(size_t)(row+8)*DIM_H + col]   + acc[mt][nt][2] + bb0);
            out[(size_t)(row+8)*DIM_H + col+1] = mv1*(g_h[(size_t)(row+8)*DIM_H + col+1] + acc[mt][nt][3] + bb1);
        }
    }
}

// ============================================================================
extern "C" void kernel_launch(void* const* d_in, const int* in_sizes, int n_in,
                              void* d_out, int out_size)
{
    const float* hV      = (const float*)d_in[0];
    const float* hE      = (const float*)d_in[1];
    const int*   Eidx    = (const int*)  d_in[2];
    const float* maskV   = (const float*)d_in[3];
    const float* maskAtt = (const float*)d_in[4];
    const float* W1  = (const float*)d_in[5];
    const float* b1  = (const float*)d_in[6];
    const float* W2  = (const float*)d_in[7];
    const float* b2  = (const float*)d_in[8];
    const float* W3  = (const float*)d_in[9];
    const float* b3  = (const float*)d_in[10];
    const float* Win = (const float*)d_in[11];
    const float* bin = (const float*)d_in[12];
    const float* Wout= (const float*)d_in[13];
    const float* bout= (const float*)d_in[14];
    float* out = (float*)d_out;

    cudaFuncSetAttribute(enc_edge_kernel, cudaFuncAttributeMaxDynamicSharedMemorySize, K1_SMEM);
    cudaFuncSetAttribute(ffn1_kernel,     cudaFuncAttributeMaxDynamicSharedMemorySize, K2_SMEM);
    cudaFuncSetAttribute(ffn2_kernel,     cudaFuncAttributeMaxDynamicSharedMemorySize, K3_SMEM);

    enc_edge_kernel<<<148, 512, K1_SMEM>>>(hV, hE, Eidx, maskAtt,
                                           W1, b1, W2, b2, W3, b3);
    ffn1_kernel<<<dim3(64, 4), 256, K2_SMEM>>>(Win, bin);
    ffn2_kernel<<<128, 256, K3_SMEM>>>(Wout, bout, maskV, out);
}

// round 5
// speedup vs baseline: 1.4623x; 1.1979x over previous
#include <cuda_runtime.h>
#include <cuda_fp16.h>
#include <cstdint>

#define NUM_B 4
#define NUM_N 2048
#define NUM_K 48
#define DIM_H 128
#define DIM_IN 256
#define DIM_FF 512
#define NODES (NUM_B*NUM_N)        // 8192
#define NPB 2
#define MROWS (NPB*NUM_K)          // 96
#define NGROUPS (NODES/NPB)        // 4096

// smem leading dims (elements): LD*2 bytes mod 128 == 16 -> 8-row ldmatrix
// phases hit banks {0,4,8,...,28}+span -> conflict-free
#define LD_A  264
#define LD_W1 264
#define LD_S  136
#define LD_WF 520

// ---- kernel1 smem offsets (bytes) ----
#define K1_OFF_W1 0                // 128*264*2 = 67584
#define K1_OFF_W2 67584            // 128*136*2 = 34816
#define K1_OFF_W3 102400           // 34816
#define K1_OFF_A  137216           // 96*264*2  = 50688
#define K1_OFF_M  187904           // 96*136*2  = 26112
#define K1_OFF_B1 214016           // 512
#define K1_OFF_B2 214528
#define K1_OFF_B3 215040
#define K1_OFF_MS 215552           // 96*4
#define K1_SMEM   216064

// ---- kernel2 smem ----
#define K2_OFF_A 0                 // 128*136*2 = 34816
#define K2_OFF_W 34816             // 34816
#define K2_OFF_B 69632             // 512
#define K2_SMEM  70144

// ---- kernel3 smem (64-row tiles) ----
#define K3_OFF_W 0                 // 128*520*2 = 133120
#define K3_OFF_A 133120            // 64*136*2 = 17408
#define K3_OFF_B 150528            // 512
#define K3_SMEM  151040

// scratch (no cudaMalloc allowed -> device globals)
__device__ float  g_h[NODES*DIM_H];            // h = h_V + dh  (fp32)
__device__ __half g_t[(size_t)NODES*DIM_FF];   // FFN intermediate (fp16)

// gelu(tanh approx) = x * sigmoid(1.59576912*x + 0.07135482*x^3), MUFU-based
__device__ __forceinline__ float gelu_tanh(float x){
    float u = fmaf(0.0713548162726009f*x, x*x, 1.5957691216057308f*x);
    u = fmaxf(u, -80.0f);                   // keep __expf(-u) finite-safe
    return __fdividef(x, 1.0f + __expf(-u));
}
__device__ __forceinline__ float gelu_erf(float x){
    return 0.5f*x*(1.0f + erff(x*0.7071067811865475f));
}

__device__ __forceinline__ uint32_t smem_u32(const void* p){
    return (uint32_t)__cvta_generic_to_shared(p);
}

__device__ __forceinline__ void mma_f16(float* c,
    uint32_t a0, uint32_t a1, uint32_t a2, uint32_t a3, uint32_t b0, uint32_t b1){
    asm volatile("mma.sync.aligned.m16n8k16.row.col.f32.f16.f16.f32 "
        "{%0,%1,%2,%3},{%4,%5,%6,%7},{%8,%9},{%0,%1,%2,%3};"
        : "+f"(c[0]), "+f"(c[1]), "+f"(c[2]), "+f"(c[3])
        : "r"(a0), "r"(a1), "r"(a2), "r"(a3), "r"(b0), "r"(b1));
}

__device__ __forceinline__ void ldsm_x4(uint32_t& r0, uint32_t& r1, uint32_t& r2, uint32_t& r3,
                                        uint32_t addr){
    asm volatile("ldmatrix.sync.aligned.m8n8.x4.shared.b16 {%0,%1,%2,%3},[%4];"
        : "=r"(r0), "=r"(r1), "=r"(r2), "=r"(r3) : "r"(addr));
}

// ldmatrix-based warp GEMM fragment.
// aAddr: per-lane smem byte addr of A[(rowbase + (lane&15))*LDA + (lane>>4)*8]
// bAddr: per-lane smem byte addr of Bt[(colbase + (lane&7)+(lane>>4)*8)*LDB + ((lane>>3)&1)*8]
// acc: flattened [MT][2*NG][4]
template<int MT, int NG, int KSTEPS, int LDA, int LDB>
__device__ __forceinline__ void gemm_lm(uint32_t aAddr, uint32_t bAddr, float (*acc)[4]){
#pragma unroll
    for (int kt = 0; kt < KSTEPS; kt++){
        uint32_t a[MT][4], b[NG][4];
#pragma unroll
        for (int mt = 0; mt < MT; mt++)
            ldsm_x4(a[mt][0], a[mt][1], a[mt][2], a[mt][3],
                    aAddr + mt*(16*LDA*2) + kt*32);
#pragma unroll
        for (int g = 0; g < NG; g++)
            ldsm_x4(b[g][0], b[g][1], b[g][2], b[g][3],
                    bAddr + g*(16*LDB*2) + kt*32);
#pragma unroll
        for (int g = 0; g < NG; g++)
#pragma unroll
            for (int mt = 0; mt < MT; mt++){
                mma_f16(acc[mt*2*NG + 2*g    ], a[mt][0], a[mt][1], a[mt][2], a[mt][3], b[g][0], b[g][1]);
                mma_f16(acc[mt*2*NG + 2*g + 1], a[mt][0], a[mt][1], a[mt][2], a[mt][3], b[g][2], b[g][3]);
            }
    }
}

// prefetch one group's gather+concat data into 24 packed half2 registers
__device__ __forceinline__ void prefetch_group(int g,
    const float* __restrict__ hV, const float* __restrict__ hE,
    const int* __restrict__ Eidx, const float* __restrict__ maskAtt,
    int tid, uint32_t* ph, float& pmask)
{
#pragma unroll
    for (int s = 0; s < 12; s++){
        int i = tid + s*512;
        int r = i >> 6, c = i & 63;        // c == tid&63 (warp-uniform branch)
        int node = g*NPB + (r >= NUM_K ? 1 : 0);
        int kk   = (r >= NUM_K) ? (r - NUM_K) : r;
        float4 v;
        if (c < 32){
            int idx = __ldg(Eidx + node*NUM_K + kk);
            int nb  = ((node >> 11) << 11) + idx;
            v = __ldg((const float4*)(hV + (size_t)nb*DIM_H) + c);
        } else {
            v = __ldg((const float4*)(hE + (size_t)(node*NUM_K + kk)*DIM_H) + (c - 32));
        }
        __half2 p0 = __floats2half2_rn(v.x, v.y);
        __half2 p1 = __floats2half2_rn(v.z, v.w);
        ph[2*s]   = *(uint32_t*)&p0;
        ph[2*s+1] = *(uint32_t*)&p1;
    }
    if (tid < MROWS){
        int node = g*NPB + (tid >= NUM_K ? 1 : 0);
        int kk   = (tid >= NUM_K) ? (tid - NUM_K) : tid;
        pmask = maskAtt[node*NUM_K + kk];
    }
}

// ============================================================================
// Kernel 1: persistent edge-MLP.  h = h_V + sum_k(mask*(MLP(h_EV)))/30
// 512 threads: warp grid 2 (node) x 8 (16-col groups); gather pipelined in regs
// ============================================================================
__global__ void __launch_bounds__(512, 1) enc_edge_kernel(
    const float* __restrict__ hV, const float* __restrict__ hE,
    const int* __restrict__ Eidx, const float* __restrict__ maskAtt,
    const float* __restrict__ W1, const float* __restrict__ b1,
    const float* __restrict__ W2, const float* __restrict__ b2,
    const float* __restrict__ W3, const float* __restrict__ b3)
{
    extern __shared__ unsigned char smem[];
    __half* sW1 = (__half*)(smem + K1_OFF_W1);
    __half* sW2 = (__half*)(smem + K1_OFF_W2);
    __half* sW3 = (__half*)(smem + K1_OFF_W3);
    __half* sA  = (__half*)(smem + K1_OFF_A);
    __half* sM  = (__half*)(smem + K1_OFF_M);
    float* sB1   = (float*)(smem + K1_OFF_B1);
    float* sB2   = (float*)(smem + K1_OFF_B2);
    float* sB3   = (float*)(smem + K1_OFF_B3);
    float* sMask = (float*)(smem + K1_OFF_MS);

    const int tid = threadIdx.x;

    // one-time weight load (transposed, fp16)
    for (int i = tid; i < DIM_IN*DIM_H; i += 512){
        int k = i >> 7, n = i & 127;
        sW1[n*LD_W1 + k] = __float2half_rn(W1[i]);
    }
    for (int i = tid; i < DIM_H*DIM_H; i += 512){
        int k = i >> 7, n = i & 127;
        sW2[n*LD_S + k] = __float2half_rn(W2[i]);
        sW3[n*LD_S + k] = __float2half_rn(W3[i]);
    }
    if (tid < 128){ sB1[tid] = b1[tid]; sB2[tid] = b2[tid]; sB3[tid] = b3[tid]; }

    const int lane = tid & 31, wid = tid >> 5;
    const int wm = wid >> 3, wn = wid & 7;      // 2 warp-rows x 8 warp-cols
    const int tg = lane >> 2, tk = lane & 3;
    const int colbase = wn*16;
    const int rowbase = wm*48;                  // warp-row wm owns one node's 48 rows

    // per-lane ldmatrix base addresses (fixed for the whole persistent loop)
    const int l15 = lane & 15, lhi = lane >> 4;
    const int b_n = (lane & 7) + lhi*8;
    const int b_k = ((lane >> 3) & 1) * 8;
    const uint32_t aA  = smem_u32(sA)  + (uint32_t)(((rowbase + l15)*LD_A  + lhi*8)*2);
    const uint32_t aM  = smem_u32(sM)  + (uint32_t)(((rowbase + l15)*LD_S  + lhi*8)*2);
    const uint32_t bW1 = smem_u32(sW1) + (uint32_t)(((colbase + b_n)*LD_W1 + b_k)*2);
    const uint32_t bW2 = smem_u32(sW2) + (uint32_t)(((colbase + b_n)*LD_S  + b_k)*2);
    const uint32_t bW3 = smem_u32(sW3) + (uint32_t)(((colbase + b_n)*LD_S  + b_k)*2);

    // pipeline prologue: prefetch first group into registers
    uint32_t ph[24];
    float pmask = 0.0f;
    prefetch_group(blockIdx.x, hV, hE, Eidx, maskAtt, tid, ph, pmask);

    for (int g = blockIdx.x; g < NGROUPS; g += gridDim.x){
        __syncthreads();   // previous iteration fully consumed sMask/sA/sM

        // drain registers -> sA [96][256] fp16 (+mask)
        if (tid < MROWS) sMask[tid] = pmask;
#pragma unroll
        for (int s = 0; s < 12; s++){
            int i = tid + s*512;
            int r = i >> 6, c = i & 63;
            __half* dst = sA + (size_t)r*LD_A + c*4;
            *(uint32_t*)dst       = ph[2*s];
            *(uint32_t*)(dst + 2) = ph[2*s+1];
        }
        __syncthreads();

        float acc[3][2][4];

        // ---- GEMM1: [96,256]x[256,128] + gelu_tanh ----
#pragma unroll
        for (int mt = 0; mt < 3; mt++)
#pragma unroll
            for (int nt = 0; nt < 2; nt++)
#pragma unroll
                for (int j = 0; j < 4; j++) acc[mt][nt][j] = 0.f;
        gemm_lm<3,1,16,LD_A,LD_W1>(aA, bW1, &acc[0][0]);

        // issue next group's gather loads now; they complete under GEMM2/3
        {
            int gn = g + gridDim.x;
            if (gn < NGROUPS)
                prefetch_group(gn, hV, hE, Eidx, maskAtt, tid, ph, pmask);
        }

#pragma unroll
        for (int nt = 0; nt < 2; nt++){
            int col = colbase + nt*8 + tk*2;
            float bb0 = sB1[col], bb1 = sB1[col+1];
#pragma unroll
            for (int mt = 0; mt < 3; mt++){
                int row = rowbase + mt*16 + tg;
                __half2 p0 = __floats2half2_rn(gelu_tanh(acc[mt][nt][0]+bb0),
                                               gelu_tanh(acc[mt][nt][1]+bb1));
                __half2 p1 = __floats2half2_rn(gelu_tanh(acc[mt][nt][2]+bb0),
                                               gelu_tanh(acc[mt][nt][3]+bb1));
                *(uint32_t*)(sM + (size_t)row*LD_S + col)     = *(uint32_t*)&p0;
                *(uint32_t*)(sM + (size_t)(row+8)*LD_S + col) = *(uint32_t*)&p1;
            }
        }
        __syncthreads();

        // ---- GEMM2: [96,128]x[128,128] + gelu_tanh ----
#pragma unroll
        for (int mt = 0; mt < 3; mt++)
#pragma unroll
            for (int nt = 0; nt < 2; nt++)
#pragma unroll
                for (int j = 0; j < 4; j++) acc[mt][nt][j] = 0.f;
        gemm_lm<3,1,8,LD_S,LD_S>(aM, bW2, &acc[0][0]);
        __syncthreads();   // all reads of sM done before overwrite
#pragma unroll
        for (int nt = 0; nt < 2; nt++){
            int col = colbase + nt*8 + tk*2;
            float bb0 = sB2[col], bb1 = sB2[col+1];
#pragma unroll
            for (int mt = 0; mt < 3; mt++){
                int row = rowbase + mt*16 + tg;
                __half2 p0 = __floats2half2_rn(gelu_tanh(acc[mt][nt][0]+bb0),
                                               gelu_tanh(acc[mt][nt][1]+bb1));
                __half2 p1 = __floats2half2_rn(gelu_tanh(acc[mt][nt][2]+bb0),
                                               gelu_tanh(acc[mt][nt][3]+bb1));
                *(uint32_t*)(sM + (size_t)row*LD_S + col)     = *(uint32_t*)&p0;
                *(uint32_t*)(sM + (size_t)(row+8)*LD_S + col) = *(uint32_t*)&p1;
            }
        }
        __syncthreads();

        // ---- GEMM3 + masked K-reduction + residual ----
#pragma unroll
        for (int mt = 0; mt < 3; mt++)
#pragma unroll
            for (int nt = 0; nt < 2; nt++)
#pragma unroll
                for (int j = 0; j < 4; j++) acc[mt][nt][j] = 0.f;
        gemm_lm<3,1,8,LD_S,LD_S>(aM, bW3, &acc[0][0]);

        float red[2][2];
#pragma unroll
        for (int nt = 0; nt < 2; nt++){ red[nt][0] = 0.f; red[nt][1] = 0.f; }
#pragma unroll
        for (int mt = 0; mt < 3; mt++){
            int row = rowbase + mt*16 + tg;
            float m0 = sMask[row], m1 = sMask[row+8];
#pragma unroll
            for (int nt = 0; nt < 2; nt++){
                int col = colbase + nt*8 + tk*2;
                float bc0 = sB3[col], bc1 = sB3[col+1];
                red[nt][0] += (acc[mt][nt][0]+bc0)*m0 + (acc[mt][nt][2]+bc0)*m1;
                red[nt][1] += (acc[mt][nt][1]+bc1)*m0 + (acc[mt][nt][3]+bc1)*m1;
            }
        }
#pragma unroll
        for (int off = 4; off < 32; off <<= 1){
#pragma unroll
            for (int nt = 0; nt < 2; nt++){
                red[nt][0] += __shfl_xor_sync(0xffffffffu, red[nt][0], off);
                red[nt][1] += __shfl_xor_sync(0xffffffffu, red[nt][1], off);
            }
        }
        if (tg == 0){
            int node = g*NPB + wm;
#pragma unroll
            for (int nt = 0; nt < 2; nt++){
                int col = colbase + nt*8 + tk*2;
                g_h[node*DIM_H + col]     = hV[node*DIM_H + col]     + red[nt][0]*(1.0f/30.0f);
                g_h[node*DIM_H + col + 1] = hV[node*DIM_H + col + 1] + red[nt][1]*(1.0f/30.0f);
            }
        }
    }
}

// ============================================================================
// Kernel 2: t = gelu_exact(h @ W_in + b_in)   [8192,128]x[128,512]
// ============================================================================
__global__ void __launch_bounds__(256) ffn1_kernel(const float* __restrict__ Win,
                                                   const float* __restrict__ bin)
{
    extern __shared__ unsigned char smem[];
    __half* sA = (__half*)(smem + K2_OFF_A);
    __half* sW = (__half*)(smem + K2_OFF_W);
    float* sB = (float*)(smem + K2_OFF_B);

    const int tid = threadIdx.x;
    const int rowb = blockIdx.x*128;
    const int nb   = blockIdx.y*128;

    for (int i = tid; i < 128*128; i += 256){
        int k = i >> 7, n = i & 127;
        sW[n*LD_S + k] = __float2half_rn(Win[(size_t)k*DIM_FF + nb + n]);
    }
    if (tid < 128) sB[tid] = bin[nb + tid];
    for (int i = tid; i < 128*32; i += 256){
        int r = i >> 5, c = i & 31;
        float4 v = ((const float4*)(g_h + (size_t)(rowb + r)*DIM_H))[c];
        __half2 p0 = __floats2half2_rn(v.x, v.y);
        __half2 p1 = __floats2half2_rn(v.z, v.w);
        __half* dst = sA + (size_t)r*LD_S + c*4;
        *(uint32_t*)dst       = *(uint32_t*)&p0;
        *(uint32_t*)(dst + 2) = *(uint32_t*)&p1;
    }
    __syncthreads();

    const int lane = tid & 31, wid = tid >> 5;
    const int wm = wid >> 2, wn = wid & 3;
    const int tg = lane >> 2, tk = lane & 3;
    const int l15 = lane & 15, lhi = lane >> 4;
    const int b_n = (lane & 7) + lhi*8;
    const int b_k = ((lane >> 3) & 1) * 8;
    const uint32_t aA = smem_u32(sA) + (uint32_t)(((wm*64 + l15)*LD_S + lhi*8)*2);
    const uint32_t bW = smem_u32(sW) + (uint32_t)(((wn*32 + b_n)*LD_S + b_k)*2);

    float acc[4][4][4];
#pragma unroll
    for (int mt = 0; mt < 4; mt++)
#pragma unroll
        for (int nt = 0; nt < 4; nt++)
#pragma unroll
            for (int j = 0; j < 4; j++) acc[mt][nt][j] = 0.f;
    gemm_lm<4,2,8,LD_S,LD_S>(aA, bW, &acc[0][0]);

#pragma unroll
    for (int nt = 0; nt < 4; nt++){
        int col = wn*32 + nt*8 + tk*2;
        float bb0 = sB[col], bb1 = sB[col+1];
#pragma unroll
        for (int mt = 0; mt < 4; mt++){
            int row = rowb + wm*64 + mt*16 + tg;
            __half2 p0 = __floats2half2_rn(gelu_erf(acc[mt][nt][0]+bb0),
                                           gelu_erf(acc[mt][nt][1]+bb1));
            __half2 p1 = __floats2half2_rn(gelu_erf(acc[mt][nt][2]+bb0),
                                           gelu_erf(acc[mt][nt][3]+bb1));
            *(__half2*)(g_t + (size_t)row*DIM_FF + nb + col)     = p0;
            *(__half2*)(g_t + (size_t)(row+8)*DIM_FF + nb + col) = p1;
        }
    }
}

// ============================================================================
// Kernel 3: out = mask_V * (h + t @ W_out + b_out)   [8192,512]x[512,128]
// 128 CTAs x 64 rows
// ============================================================================
__global__ void __launch_bounds__(256) ffn2_kernel(const float* __restrict__ Wout,
                                                   const float* __restrict__ bout,
                                                   const float* __restrict__ maskV,
                                                   float* __restrict__ out)
{
    extern __shared__ unsigned char smem[];
    __half* sW = (__half*)(smem + K3_OFF_W);
    __half* sA = (__half*)(smem + K3_OFF_A);
    float* sB = (float*)(smem + K3_OFF_B);

    const int tid = threadIdx.x;
    const int rowb = blockIdx.x*64;

    for (int i = tid; i < DIM_FF*DIM_H; i += 256){
        int k = i >> 7, n = i & 127;
        sW[(size_t)n*LD_WF + k] = __float2half_rn(Wout[(size_t)k*DIM_H + n]);
    }
    if (tid < 128) sB[tid] = bout[tid];

    const int lane = tid & 31, wid = tid >> 5;
    const int wm = wid >> 2, wn = wid & 3;
    const int tg = lane >> 2, tk = lane & 3;
    const int l15 = lane & 15, lhi = lane >> 4;
    const int b_n = (lane & 7) + lhi*8;
    const int b_k = ((lane >> 3) & 1) * 8;
    const uint32_t aA = smem_u32(sA) + (uint32_t)(((wm*32 + l15)*LD_S + lhi*8)*2);
    const uint32_t bW = smem_u32(sW) + (uint32_t)(((wn*32 + b_n)*LD_WF + b_k)*2);

    float acc[2][4][4];
#pragma unroll
    for (int mt = 0; mt < 2; mt++)
#pragma unroll
        for (int nt = 0; nt < 4; nt++)
#pragma unroll
            for (int j = 0; j < 4; j++) acc[mt][nt][j] = 0.f;

    for (int kc = 0; kc < 4; kc++){
        __syncthreads();
        for (int i = tid; i < 64*16; i += 256){
            int r = i >> 4, c = i & 15;
            uint4 v = ((const uint4*)(g_t + (size_t)(rowb + r)*DIM_FF + kc*128))[c];
            *(uint4*)(sA + (size_t)r*LD_S + c*8) = v;
        }
        __syncthreads();
        gemm_lm<2,2,8,LD_S,LD_WF>(aA, bW + kc*128*2, &acc[0][0]);
    }

#pragma unroll
    for (int nt = 0; nt < 4; nt++){
        int col = wn*32 + nt*8 + tk*2;
        float bb0 = sB[col], bb1 = sB[col+1];
#pragma unroll
        for (int mt = 0; mt < 2; mt++){
            int row = rowb + wm*32 + mt*16 + tg;
            float mv0 = maskV[row], mv1 = maskV[row+8];
            out[(size_t)row*DIM_H + col]       = mv0*(g_h[(size_t)row*DIM_H + col]       + acc[mt][nt][0] + bb0);
            out[(size_t)row*DIM_H + col + 1]   = mv0*(g_h[(size_t)row*DIM_H + col + 1]   + acc[mt][nt][1] + bb1);
            out[(size_t)(row+8)*DIM_H + col]   = mv1*(g_h[(size_t)(row+8)*DIM_H + col]   + acc[mt][nt][2] + bb0);
            out[(size_t)(row+8)*DIM_H + col+1] = mv1*(g_h[(size_t)(row+8)*DIM_H + col+1] + acc[mt][nt][3] + bb1);
        }
    }
}

// ============================================================================
extern "C" void kernel_launch(void* const* d_in, const int* in_sizes, int n_in,
                              void* d_out, int out_size)
{
    const float* hV      = (const float*)d_in[0];
    const float* hE      = (const float*)d_in[1];
    const int*   Eidx    = (const int*)  d_in[2];
    const float* maskV   = (const float*)d_in[3];
    const float* maskAtt = (const float*)d_in[4];
    const float* W1  = (const float*)d_in[5];
    const float* b1  = (const float*)d_in[6];
    const float* W2  = (const float*)d_in[7];
    const float* b2  = (const float*)d_in[8];
    const float* W3  = (const float*)d_in[9];
    const float* b3  = (const float*)d_in[10];
    const float* Win = (const float*)d_in[11];
    const float* bin = (const float*)d_in[12];
    const float* Wout= (const float*)d_in[13];
    const float* bout= (const float*)d_in[14];
    float* out = (float*)d_out;

    cudaFuncSetAttribute(enc_edge_kernel, cudaFuncAttributeMaxDynamicSharedMemorySize, K1_SMEM);
    cudaFuncSetAttribute(ffn1_kernel,     cudaFuncAttributeMaxDynamicSharedMemorySize, K2_SMEM);
    cudaFuncSetAttribute(ffn2_kernel,     cudaFuncAttributeMaxDynamicSharedMemorySize, K3_SMEM);

    enc_edge_kernel<<<148, 512, K1_SMEM>>>(hV, hE, Eidx, maskAtt,
                                           W1, b1, W2, b2, W3, b3);
    ffn1_kernel<<<dim3(64, 4), 256, K2_SMEM>>>(Win, bin);
    ffn2_kernel<<<128, 256, K3_SMEM>>>(Wout, bout, maskV, out);
}

// round 7
// speedup vs baseline: 1.5981x; 1.0929x over previous
#include <cuda_runtime.h>
#include <cuda_fp16.h>
#include <cstdint>

#define NUM_B 4
#define NUM_N 2048
#define NUM_K 48
#define DIM_H 128
#define DIM_IN 256
#define DIM_FF 512
#define NODES (NUM_B*NUM_N)        // 8192

// smem leading dims (elements): LD*2 bytes mod 128 == 16 -> 8-row ldmatrix
// phases hit banks {0,4,8,...,28}+span -> conflict-free
#define LD_A  264
#define LD_W1 264
#define LD_S  136
#define LD_WF 520

// ---- kernel1 smem: shared weights + two independent half-pipelines ----
#define KH_W1 0                    // 128*264*2 = 67584
#define KH_W2 67584                // 128*136*2 = 34816
#define KH_W3 102400               // 34816
#define KH_B1 137216               // 512
#define KH_B2 137728
#define KH_B3 138240
#define KH_HBASE 138752
#define KH_A_SZ  25344             // 48*264*2
#define KH_M_SZ  13056             // 48*136*2
#define KH_HSIZE 38656             // A + M + mask(192) + pad
#define K1_SMEM  (KH_HBASE + 2*KH_HSIZE)   // 216064

// ---- kernel2 smem ----
#define K2_OFF_A 0
#define K2_OFF_W 34816
#define K2_OFF_B 69632
#define K2_SMEM  70144

// ---- kernel3 smem (64-row tiles) ----
#define K3_OFF_W 0
#define K3_OFF_A 133120
#define K3_OFF_B 150528
#define K3_SMEM  151040

__device__ float  g_h[NODES*DIM_H];
__device__ __half g_t[(size_t)NODES*DIM_FF];

__device__ __forceinline__ float gelu_tanh(float x){
    float u = fmaf(0.0713548162726009f*x, x*x, 1.5957691216057308f*x);
    u = fmaxf(u, -80.0f);
    return __fdividef(x, 1.0f + __expf(-u));
}
__device__ __forceinline__ float gelu_erf(float x){
    return 0.5f*x*(1.0f + erff(x*0.7071067811865475f));
}
__device__ __forceinline__ uint32_t smem_u32(const void* p){
    return (uint32_t)__cvta_generic_to_shared(p);
}
#define BARH(id) asm volatile("bar.sync %0, 256;" :: "r"(id) : "memory")

__device__ __forceinline__ void mma_f16(float* c,
    uint32_t a0, uint32_t a1, uint32_t a2, uint32_t a3, uint32_t b0, uint32_t b1){
    asm volatile("mma.sync.aligned.m16n8k16.row.col.f32.f16.f16.f32 "
        "{%0,%1,%2,%3},{%4,%5,%6,%7},{%8,%9},{%0,%1,%2,%3};"
        : "+f"(c[0]), "+f"(c[1]), "+f"(c[2]), "+f"(c[3])
        : "r"(a0), "r"(a1), "r"(a2), "r"(a3), "r"(b0), "r"(b1));
}
__device__ __forceinline__ void ldsm_x4(uint32_t& r0, uint32_t& r1, uint32_t& r2, uint32_t& r3,
                                        uint32_t addr){
    asm volatile("ldmatrix.sync.aligned.m8n8.x4.shared.b16 {%0,%1,%2,%3},[%4];"
        : "=r"(r0), "=r"(r1), "=r"(r2), "=r"(r3) : "r"(addr));
}

// ldmatrix-based warp GEMM fragment (see R5 comments for lane mapping)
template<int MT, int NG, int KSTEPS, int LDA, int LDB>
__device__ __forceinline__ void gemm_lm(uint32_t aAddr, uint32_t bAddr, float (*acc)[4]){
#pragma unroll
    for (int kt = 0; kt < KSTEPS; kt++){
        uint32_t a[MT][4], b[NG][4];
#pragma unroll
        for (int mt = 0; mt < MT; mt++)
            ldsm_x4(a[mt][0], a[mt][1], a[mt][2], a[mt][3],
                    aAddr + mt*(16*LDA*2) + kt*32);
#pragma unroll
        for (int g = 0; g < NG; g++)
            ldsm_x4(b[g][0], b[g][1], b[g][2], b[g][3],
                    bAddr + g*(16*LDB*2) + kt*32);
#pragma unroll
        for (int g = 0; g < NG; g++)
#pragma unroll
            for (int mt = 0; mt < MT; mt++){
                mma_f16(acc[mt*2*NG + 2*g    ], a[mt][0], a[mt][1], a[mt][2], a[mt][3], b[g][0], b[g][1]);
                mma_f16(acc[mt*2*NG + 2*g + 1], a[mt][0], a[mt][1], a[mt][2], a[mt][3], b[g][2], b[g][3]);
            }
    }
}

// prefetch one node's gather+concat data into 24 packed half2 regs (per-half, 256 thr)
__device__ __forceinline__ void prefetch_node(int node,
    const float* __restrict__ hV, const float* __restrict__ hE,
    const int* __restrict__ Eidx, const float* __restrict__ maskAtt,
    int htid, uint32_t* ph, float& pmask)
{
#pragma unroll
    for (int s = 0; s < 12; s++){
        int i = htid + s*256;
        int r = i >> 6, c = i & 63;
        float4 v;
        if (c < 32){
            int idx = __ldg(Eidx + node*NUM_K + r);
            int nb  = ((node >> 11) << 11) + idx;
            v = __ldg((const float4*)(hV + (size_t)nb*DIM_H) + c);
        } else {
            v = __ldg((const float4*)(hE + (size_t)(node*NUM_K + r)*DIM_H) + (c - 32));
        }
        __half2 p0 = __floats2half2_rn(v.x, v.y);
        __half2 p1 = __floats2half2_rn(v.z, v.w);
        ph[2*s]   = *(uint32_t*)&p0;
        ph[2*s+1] = *(uint32_t*)&p1;
    }
    if (htid < NUM_K) pmask = maskAtt[node*NUM_K + htid];
}

// ============================================================================
// Kernel 1: persistent edge-MLP, two independent 256-thread half-pipelines
// sharing one smem weight copy.  h = h_V + sum_k(mask*MLP(h_EV))/30
// ============================================================================
__global__ void __launch_bounds__(512, 1) enc_edge_kernel(
    const float* __restrict__ hV, const float* __restrict__ hE,
    const int* __restrict__ Eidx, const float* __restrict__ maskAtt,
    const float* __restrict__ W1, const float* __restrict__ b1,
    const float* __restrict__ W2, const float* __restrict__ b2,
    const float* __restrict__ W3, const float* __restrict__ b3)
{
    extern __shared__ unsigned char smem[];
    __half* sW1 = (__half*)(smem + KH_W1);
    __half* sW2 = (__half*)(smem + KH_W2);
    __half* sW3 = (__half*)(smem + KH_W3);
    float* sB1 = (float*)(smem + KH_B1);
    float* sB2 = (float*)(smem + KH_B2);
    float* sB3 = (float*)(smem + KH_B3);

    const int tid  = threadIdx.x;
    const int half = tid >> 8;                 // warps 0-7 | 8-15
    const int htid = tid & 255;
    const int lane = tid & 31;
    const int hw   = (tid >> 5) & 7;           // warp-col within half (16 cols)
    const int tg = lane >> 2, tk = lane & 3;
    const int colbase = hw*16;
    const int barid = 1 + half;

    unsigned char* hbuf = smem + KH_HBASE + half*KH_HSIZE;
    __half* sA    = (__half*)(hbuf);
    __half* sM    = (__half*)(hbuf + KH_A_SZ);
    float*  sMask = (float*) (hbuf + KH_A_SZ + KH_M_SZ);

    // one-time weight load (all 512 threads), block-wide sync
    for (int i = tid; i < DIM_IN*DIM_H; i += 512){
        int k = i >> 7, n = i & 127;
        sW1[n*LD_W1 + k] = __float2half_rn(W1[i]);
    }
    for (int i = tid; i < DIM_H*DIM_H; i += 512){
        int k = i >> 7, n = i & 127;
        sW2[n*LD_S + k] = __float2half_rn(W2[i]);
        sW3[n*LD_S + k] = __float2half_rn(W3[i]);
    }
    if (tid < 128){ sB1[tid] = b1[tid]; sB2[tid] = b2[tid]; sB3[tid] = b3[tid]; }
    __syncthreads();

    // per-lane ldmatrix base addresses (48-row tiles, rowbase 0)
    const int l15 = lane & 15, lhi = lane >> 4;
    const int b_n = (lane & 7) + lhi*8;
    const int b_k = ((lane >> 3) & 1) * 8;
    const uint32_t aA  = smem_u32(sA)  + (uint32_t)((l15*LD_A + lhi*8)*2);
    const uint32_t aM  = smem_u32(sM)  + (uint32_t)((l15*LD_S + lhi*8)*2);
    const uint32_t bW1 = smem_u32(sW1) + (uint32_t)(((colbase + b_n)*LD_W1 + b_k)*2);
    const uint32_t bW2 = smem_u32(sW2) + (uint32_t)(((colbase + b_n)*LD_S  + b_k)*2);
    const uint32_t bW3 = smem_u32(sW3) + (uint32_t)(((colbase + b_n)*LD_S  + b_k)*2);

    const int stride = 2*gridDim.x;
    uint32_t ph[24];
    float pmask = 0.0f;
    prefetch_node(blockIdx.x*2 + half, hV, hE, Eidx, maskAtt, htid, ph, pmask);

    for (int g = blockIdx.x*2 + half; g < NODES; g += stride){
        BARH(barid);   // previous iteration fully consumed sMask/sA/sM

        if (htid < NUM_K) sMask[htid] = pmask;
#pragma unroll
        for (int s = 0; s < 12; s++){
            int i = htid + s*256;
            int r = i >> 6, c = i & 63;
            __half* dst = sA + (size_t)r*LD_A + c*4;
            *(uint32_t*)dst       = ph[2*s];
            *(uint32_t*)(dst + 2) = ph[2*s+1];
        }
        BARH(barid);

        float acc[3][2][4];

        // ---- GEMM1: [48,256]x[256,128] + gelu_tanh ----
#pragma unroll
        for (int mt = 0; mt < 3; mt++)
#pragma unroll
            for (int nt = 0; nt < 2; nt++)
#pragma unroll
                for (int j = 0; j < 4; j++) acc[mt][nt][j] = 0.f;
        gemm_lm<3,1,16,LD_A,LD_W1>(aA, bW1, &acc[0][0]);

        // issue next node's gather loads; complete under GEMM2/3
        {
            int gn = g + stride;
            if (gn < NODES) prefetch_node(gn, hV, hE, Eidx, maskAtt, htid, ph, pmask);
        }

#pragma unroll
        for (int nt = 0; nt < 2; nt++){
            int col = colbase + nt*8 + tk*2;
            float bb0 = sB1[col], bb1 = sB1[col+1];
#pragma unroll
            for (int mt = 0; mt < 3; mt++){
                int row = mt*16 + tg;
                __half2 p0 = __floats2half2_rn(gelu_tanh(acc[mt][nt][0]+bb0),
                                               gelu_tanh(acc[mt][nt][1]+bb1));
                __half2 p1 = __floats2half2_rn(gelu_tanh(acc[mt][nt][2]+bb0),
                                               gelu_tanh(acc[mt][nt][3]+bb1));
                *(uint32_t*)(sM + (size_t)row*LD_S + col)     = *(uint32_t*)&p0;
                *(uint32_t*)(sM + (size_t)(row+8)*LD_S + col) = *(uint32_t*)&p1;
            }
        }
        BARH(barid);

        // ---- GEMM2: [48,128]x[128,128] + gelu_tanh ----
#pragma unroll
        for (int mt = 0; mt < 3; mt++)
#pragma unroll
            for (int nt = 0; nt < 2; nt++)
#pragma unroll
                for (int j = 0; j < 4; j++) acc[mt][nt][j] = 0.f;
        gemm_lm<3,1,8,LD_S,LD_S>(aM, bW2, &acc[0][0]);
        BARH(barid);   // all reads of sM done before overwrite
#pragma unroll
        for (int nt = 0; nt < 2; nt++){
            int col = colbase + nt*8 + tk*2;
            float bb0 = sB2[col], bb1 = sB2[col+1];
#pragma unroll
            for (int mt = 0; mt < 3; mt++){
                int row = mt*16 + tg;
                __half2 p0 = __floats2half2_rn(gelu_tanh(acc[mt][nt][0]+bb0),
                                               gelu_tanh(acc[mt][nt][1]+bb1));
                __half2 p1 = __floats2half2_rn(gelu_tanh(acc[mt][nt][2]+bb0),
                                               gelu_tanh(acc[mt][nt][3]+bb1));
                *(uint32_t*)(sM + (size_t)row*LD_S + col)     = *(uint32_t*)&p0;
                *(uint32_t*)(sM + (size_t)(row+8)*LD_S + col) = *(uint32_t*)&p1;
            }
        }
        BARH(barid);

        // ---- GEMM3 + masked K-reduction + residual ----
#pragma unroll
        for (int mt = 0; mt < 3; mt++)
#pragma unroll
            for (int nt = 0; nt < 2; nt++)
#pragma unroll
                for (int j = 0; j < 4; j++) acc[mt][nt][j] = 0.f;
        gemm_lm<3,1,8,LD_S,LD_S>(aM, bW3, &acc[0][0]);

        float red[2][2];
#pragma unroll
        for (int nt = 0; nt < 2; nt++){ red[nt][0] = 0.f; red[nt][1] = 0.f; }
#pragma unroll
        for (int mt = 0; mt < 3; mt++){
            int row = mt*16 + tg;
            float m0 = sMask[row], m1 = sMask[row+8];
#pragma unroll
            for (int nt = 0; nt < 2; nt++){
                int col = colbase + nt*8 + tk*2;
                float bc0 = sB3[col], bc1 = sB3[col+1];
                red[nt][0] += (acc[mt][nt][0]+bc0)*m0 + (acc[mt][nt][2]+bc0)*m1;
                red[nt][1] += (acc[mt][nt][1]+bc1)*m0 + (acc[mt][nt][3]+bc1)*m1;
            }
        }
#pragma unroll
        for (int off = 4; off < 32; off <<= 1){
#pragma unroll
            for (int nt = 0; nt < 2; nt++){
                red[nt][0] += __shfl_xor_sync(0xffffffffu, red[nt][0], off);
                red[nt][1] += __shfl_xor_sync(0xffffffffu, red[nt][1], off);
            }
        }
        if (tg == 0){
#pragma unroll
            for (int nt = 0; nt < 2; nt++){
                int col = colbase + nt*8 + tk*2;
                g_h[g*DIM_H + col]     = hV[g*DIM_H + col]     + red[nt][0]*(1.0f/30.0f);
                g_h[g*DIM_H + col + 1] = hV[g*DIM_H + col + 1] + red[nt][1]*(1.0f/30.0f);
            }
        }
    }
}

// ============================================================================
// Kernel 2: t = gelu_exact(h @ W_in + b_in)   [8192,128]x[128,512]
// ============================================================================
__global__ void __launch_bounds__(256) ffn1_kernel(const float* __restrict__ Win,
                                                   const float* __restrict__ bin)
{
    extern __shared__ unsigned char smem[];
    __half* sA = (__half*)(smem + K2_OFF_A);
    __half* sW = (__half*)(smem + K2_OFF_W);
    float* sB = (float*)(smem + K2_OFF_B);

    const int tid = threadIdx.x;
    const int rowb = blockIdx.x*128;
    const int nb   = blockIdx.y*128;

    for (int i = tid; i < 128*128; i += 256){
        int k = i >> 7, n = i & 127;
        sW[n*LD_S + k] = __float2half_rn(Win[(size_t)k*DIM_FF + nb + n]);
    }
    if (tid < 128) sB[tid] = bin[nb + tid];
    for (int i = tid; i < 128*32; i += 256){
        int r = i >> 5, c = i & 31;
        float4 v = ((const float4*)(g_h + (size_t)(rowb + r)*DIM_H))[c];
        __half2 p0 = __floats2half2_rn(v.x, v.y);
        __half2 p1 = __floats2half2_rn(v.z, v.w);
        __half* dst = sA + (size_t)r*LD_S + c*4;
        *(uint32_t*)dst       = *(uint32_t*)&p0;
        *(uint32_t*)(dst + 2) = *(uint32_t*)&p1;
    }
    __syncthreads();

    const int lane = tid & 31, wid = tid >> 5;
    const int wm = wid >> 2, wn = wid & 3;
    const int tg = lane >> 2, tk = lane & 3;
    const int l15 = lane & 15, lhi = lane >> 4;
    const int b_n = (lane & 7) + lhi*8;
    const int b_k = ((lane >> 3) & 1) * 8;
    const uint32_t aA = smem_u32(sA) + (uint32_t)(((wm*64 + l15)*LD_S + lhi*8)*2);
    const uint32_t bW = smem_u32(sW) + (uint32_t)(((wn*32 + b_n)*LD_S + b_k)*2);

    float acc[4][4][4];
#pragma unroll
    for (int mt = 0; mt < 4; mt++)
#pragma unroll
        for (int nt = 0; nt < 4; nt++)
#pragma unroll
            for (int j = 0; j < 4; j++) acc[mt][nt][j] = 0.f;
    gemm_lm<4,2,8,LD_S,LD_S>(aA, bW, &acc[0][0]);

#pragma unroll
    for (int nt = 0; nt < 4; nt++){
        int col = wn*32 + nt*8 + tk*2;
        float bb0 = sB[col], bb1 = sB[col+1];
#pragma unroll
        for (int mt = 0; mt < 4; mt++){
            int row = rowb + wm*64 + mt*16 + tg;
            __half2 p0 = __floats2half2_rn(gelu_erf(acc[mt][nt][0]+bb0),
                                           gelu_erf(acc[mt][nt][1]+bb1));
            __half2 p1 = __floats2half2_rn(gelu_erf(acc[mt][nt][2]+bb0),
                                           gelu_erf(acc[mt][nt][3]+bb1));
            *(__half2*)(g_t + (size_t)row*DIM_FF + nb + col)     = p0;
            *(__half2*)(g_t + (size_t)(row+8)*DIM_FF + nb + col) = p1;
        }
    }
}

// ============================================================================
// Kernel 3: out = mask_V * (h + t @ W_out + b_out)   [8192,512]x[512,128]
// ============================================================================
__global__ void __launch_bounds__(256) ffn2_kernel(const float* __restrict__ Wout,
                                                   const float* __restrict__ bout,
                                                   const float* __restrict__ maskV,
                                                   float* __restrict__ out)
{
    extern __shared__ unsigned char smem[];
    __half* sW = (__half*)(smem + K3_OFF_W);
    __half* sA = (__half*)(smem + K3_OFF_A);
    float* sB = (float*)(smem + K3_OFF_B);

    const int tid = threadIdx.x;
    const int rowb = blockIdx.x*64;

    for (int i = tid; i < DIM_FF*DIM_H; i += 256){
        int k = i >> 7, n = i & 127;
        sW[(size_t)n*LD_WF + k] = __float2half_rn(Wout[(size_t)k*DIM_H + n]);
    }
    if (tid < 128) sB[tid] = bout[tid];

    const int lane = tid & 31, wid = tid >> 5;
    const int wm = wid >> 2, wn = wid & 3;
    const int tg = lane >> 2, tk = lane & 3;
    const int l15 = lane & 15, lhi = lane >> 4;
    const int b_n = (lane & 7) + lhi*8;
    const int b_k = ((lane >> 3) & 1) * 8;
    const uint32_t aA = smem_u32(sA) + (uint32_t)(((wm*32 + l15)*LD_S + lhi*8)*2);
    const uint32_t bW = smem_u32(sW) + (uint32_t)(((wn*32 + b_n)*LD_WF + b_k)*2);

    float acc[2][4][4];
#pragma unroll
    for (int mt = 0; mt < 2; mt++)
#pragma unroll
        for (int nt = 0; nt < 4; nt++)
#pragma unroll
            for (int j = 0; j < 4; j++) acc[mt][nt][j] = 0.f;

    for (int kc = 0; kc < 4; kc++){
        __syncthreads();
        for (int i = tid; i < 64*16; i += 256){
            int r = i >> 4, c = i & 15;
            uint4 v = ((const uint4*)(g_t + (size_t)(rowb + r)*DIM_FF + kc*128))[c];
            *(uint4*)(sA + (size_t)r*LD_S + c*8) = v;
        }
        __syncthreads();
        gemm_lm<2,2,8,LD_S,LD_WF>(aA, bW + kc*128*2, &acc[0][0]);
    }

#pragma unroll
    for (int nt = 0; nt < 4; nt++){
        int col = wn*32 + nt*8 + tk*2;
        float bb0 = sB[col], bb1 = sB[col+1];
#pragma unroll
        for (int mt = 0; mt < 2; mt++){
            int row = rowb + wm*32 + mt*16 + tg;
            float mv0 = maskV[row], mv1 = maskV[row+8];
            out[(size_t)row*DIM_H + col]       = mv0*(g_h[(size_t)row*DIM_H + col]       + acc[mt][nt][0] + bb0);
            out[(size_t)row*DIM_H + col + 1]   = mv0*(g_h[(size_t)row*DIM_H + col + 1]   + acc[mt][nt][1] + bb1);
            out[(size_t)(row+8)*DIM_H + col]   = mv1*(g_h[(size_t)(row+8)*DIM_H + col]   + acc[mt][nt][2] + bb0);
            out[(size_t)(row+8)*DIM_H + col+1] = mv1*(g_h[(size_t)(row+8)*DIM_H + col+1] + acc[mt][nt][3] + bb1);
        }
    }
}

// ============================================================================
extern "C" void kernel_launch(void* const* d_in, const int* in_sizes, int n_in,
                              void* d_out, int out_size)
{
    const float* hV      = (const float*)d_in[0];
    const float* hE      = (const float*)d_in[1];
    const int*   Eidx    = (const int*)  d_in[2];
    const float* maskV   = (const float*)d_in[3];
    const float* maskAtt = (const float*)d_in[4];
    const float* W1  = (const float*)d_in[5];
    const float* b1  = (const float*)d_in[6];
    const float* W2  = (const float*)d_in[7];
    const float* b2  = (const float*)d_in[8];
    const float* W3  = (const float*)d_in[9];
    const float* b3  = (const float*)d_in[10];
    const float* Win = (const float*)d_in[11];
    const float* bin = (const float*)d_in[12];
    const float* Wout= (const float*)d_in[13];
    const float* bout= (const float*)d_in[14];
    float* out = (float*)d_out;

    cudaFuncSetAttribute(enc_edge_kernel, cudaFuncAttributeMaxDynamicSharedMemorySize, K1_SMEM);
    cudaFuncSetAttribute(ffn1_kernel,     cudaFuncAttributeMaxDynamicSharedMemorySize, K2_SMEM);
    cudaFuncSetAttribute(ffn2_kernel,     cudaFuncAttributeMaxDynamicSharedMemorySize, K3_SMEM);

    enc_edge_kernel<<<148, 512, K1_SMEM>>>(hV, hE, Eidx, maskAtt,
                                           W1, b1, W2, b2, W3, b3);
    ffn1_kernel<<<dim3(64, 4), 256, K2_SMEM>>>(Win, bin);
    ffn2_kernel<<<128, 256, K3_SMEM>>>(Wout, bout, maskV, out);
}